// round 15
// baseline (speedup 1.0000x reference)
#include <cuda_runtime.h>
#include <cuda_fp16.h>
#include <stdint.h>

// Shapes fixed by the problem: N=4, H=W=64, C_in=256, C_red=64
constexpr int HW   = 4096;
constexpr int CIN  = 256;
constexpr int CR   = 64;
constexpr int MAXN = 4;
constexpr float LOG2E = 1.4426950408889634f;
constexpr float LN2   = 0.6931471805599453f;

// ---------------- device scratch (allocation-free) ----------------
__device__ __half g_Wah[CR * CIN];                        // f16 [cr][cout], pre-scaled by 1/64
__device__ uint32_t g_Wfrag[2 * 12288];                   // qkv weights in B-fragment order (f16x2)
__device__ float g_b192[192];
__device__ __half g_Qh[(size_t)MAXN * HW * CR];           // [n*HW + j][c]
__device__ __half g_Kh[(size_t)MAXN * HW * CR];           // [n*HW + i][c], pre-scaled by log2e
__device__ __half g_Vth[(size_t)MAXN * CR * HW];          // [n][c][i] -> scaled to V''=V*64/rowsum
__device__ float g_Mp[32 * MAXN * 4096];                  // M partials per j-chunk
__device__ float g_up[32 * MAXN * 64];                    // u partials
__device__ __half g_attph[4][(size_t)MAXN * HW * CR];     // att partials [ih][n][j][c] (64x att)

// ---------------- helpers ----------------
__device__ __forceinline__ uint32_t s2u(const void* p) {
    return (uint32_t)__cvta_generic_to_shared(p);
}
__device__ __forceinline__ void mma16816(float& c0, float& c1, float& c2, float& c3,
                                         uint32_t a0, uint32_t a1, uint32_t a2, uint32_t a3,
                                         uint32_t b0, uint32_t b1) {
    asm volatile("mma.sync.aligned.m16n8k16.row.col.f32.f16.f16.f32 "
                 "{%0,%1,%2,%3}, {%4,%5,%6,%7}, {%8,%9}, {%0,%1,%2,%3};"
                 : "+f"(c0), "+f"(c1), "+f"(c2), "+f"(c3)
                 : "r"(a0), "r"(a1), "r"(a2), "r"(a3), "r"(b0), "r"(b1));
}
__device__ __forceinline__ void mma16816h(uint32_t& d0, uint32_t& d1,
                                          uint32_t a0, uint32_t a1, uint32_t a2, uint32_t a3,
                                          uint32_t b0, uint32_t b1) {
    asm volatile("mma.sync.aligned.m16n8k16.row.col.f16.f16.f16.f16 "
                 "{%0,%1}, {%2,%3,%4,%5}, {%6,%7}, {%0,%1};"
                 : "+r"(d0), "+r"(d1)
                 : "r"(a0), "r"(a1), "r"(a2), "r"(a3), "r"(b0), "r"(b1));
}
__device__ __forceinline__ uint32_t packf16(float lo, float hi) {
    uint32_t d;
    asm("cvt.rn.f16x2.f32 %0, %1, %2;" : "=r"(d) : "f"(hi), "f"(lo));
    return d;
}
__device__ __forceinline__ float2 unpackh2(uint32_t u) {
    __half2 h = *reinterpret_cast<__half2*>(&u);
    return __half22float2(h);
}
__device__ __forceinline__ uint32_t ex2h2(uint32_t x) {
    uint32_t d;
    asm("ex2.approx.f16x2 %0, %1;" : "=r"(d) : "r"(x));
    return d;
}
__device__ __forceinline__ void cpasync16(uint32_t saddr, const void* g) {
    asm volatile("cp.async.ca.shared.global [%0], [%1], 16;" :: "r"(saddr), "l"(g));
}
__device__ __forceinline__ void cpcommit() { asm volatile("cp.async.commit_group;"); }
template<int N> __device__ __forceinline__ void cpwait() {
    asm volatile("cp.async.wait_group %0;" :: "n"(N));
}
__device__ __forceinline__ void ldsm_x4(uint32_t& r0, uint32_t& r1, uint32_t& r2, uint32_t& r3,
                                        uint32_t addr) {
    asm volatile("ldmatrix.sync.aligned.m8n8.x4.shared.b16 {%0,%1,%2,%3}, [%4];"
                 : "=r"(r0), "=r"(r1), "=r"(r2), "=r"(r3) : "r"(addr));
}

// ---------------------------------------------------------------------------
// 1) fold: Wa (f16, /64), bias, qkv weights in B-frag order; K scaled log2e
// ---------------------------------------------------------------------------
__global__ void fold_k(const float* __restrict__ dwq, const float* __restrict__ pwq,
                       const float* __restrict__ bq,
                       const float* __restrict__ dwk, const float* __restrict__ pwk,
                       const float* __restrict__ bk,
                       const float* __restrict__ dwv, const float* __restrict__ pwv,
                       const float* __restrict__ bv,
                       const float* __restrict__ dwa, const float* __restrict__ pwa) {
    const int idx = blockIdx.x * 256 + threadIdx.x;   // 0..24575
    if (idx < 16384) {
        const int cr = idx >> 8;
        g_Wah[idx] = __float2half(dwa[cr] * pwa[idx] * 0.015625f);   // 1/64 compensates V''
    }
    if (idx < 192)
        g_b192[idx] = (idx < 64) ? bq[idx]
                    : (idx < 128 ? bk[idx - 64] * LOG2E : bv[idx - 128]);

    const int nn = idx >> 7;       // output unit 0..191
    const int p  = idx & 127;      // c-pair 0..127
    const int c0 = 2 * p, c1 = 2 * p + 1;
    float w0, w1;
    if (nn < 64)       { w0 = dwq[c0] * pwq[c0 * 64 + nn];        w1 = dwq[c1] * pwq[c1 * 64 + nn]; }
    else if (nn < 128) { const int m = nn - 64;
                         w0 = dwk[c0] * pwk[c0 * 64 + m] * LOG2E;
                         w1 = dwk[c1] * pwk[c1 * 64 + m] * LOG2E; }
    else               { const int m = nn - 128; w0 = dwv[c0] * pwv[c0 * 64 + m]; w1 = dwv[c1] * pwv[c1 * 64 + m]; }
    const int h = nn / 96, nl = nn % 96, nt = nl >> 3, r = nl & 7;
    const int ks = p >> 3, rem = p & 7, q = rem & 3, slot = rem >> 2;
    g_Wfrag[(((h * 12 + nt) * 16 + ks) * 32 + r * 4 + q) * 2 + slot] = packf16(w0, w1);
}

// ---------------------------------------------------------------------------
// 2) QKV projection via mma.sync (proven R6/R10)
// ---------------------------------------------------------------------------
__global__ __launch_bounds__(256) void proj_k(const float* __restrict__ X) {
    __shared__ uint32_t sW[12288];   // 48 KB
    const int tid = threadIdx.x, lane = tid & 31, w = tid >> 5;
    const int r = lane >> 2, q = lane & 3;
    const int m0 = blockIdx.x * 128, h = blockIdx.y;

    const uint32_t swb = s2u(sW);
    const uint32_t* Wsrc = g_Wfrag + h * 12288;
    for (int t = tid; t < 3072; t += 256) cpasync16(swb + t * 16, Wsrc + t * 4);
    cpcommit(); cpwait<0>(); __syncthreads();

    float acc[12][4];
#pragma unroll
    for (int nt = 0; nt < 12; nt++) {
        const int n0 = h * 96 + nt * 8 + 2 * q;
        const float b0 = g_b192[n0], b1 = g_b192[n0 + 1];
        acc[nt][0] = b0; acc[nt][1] = b1; acc[nt][2] = b0; acc[nt][3] = b1;
    }

    const int mA = m0 + 16 * w + r;
    const float2* X2 = (const float2*)X;
    const uint2* sW2 = (const uint2*)sW;
#pragma unroll 4
    for (int ks = 0; ks < 16; ks++) {
        const float2 u0 = X2[(size_t)mA * 128 + ks * 8 + q];
        const float2 u1 = X2[(size_t)(mA + 8) * 128 + ks * 8 + q];
        const float2 u2 = X2[(size_t)mA * 128 + ks * 8 + q + 4];
        const float2 u3 = X2[(size_t)(mA + 8) * 128 + ks * 8 + q + 4];
        const uint32_t a0 = packf16(u0.x, u0.y);
        const uint32_t a1 = packf16(u1.x, u1.y);
        const uint32_t a2 = packf16(u2.x, u2.y);
        const uint32_t a3 = packf16(u3.x, u3.y);
#pragma unroll
        for (int nt = 0; nt < 12; nt++) {
            const uint2 b = sW2[(nt * 16 + ks) * 32 + lane];
            mma16816(acc[nt][0], acc[nt][1], acc[nt][2], acc[nt][3], a0, a1, a2, a3, b.x, b.y);
        }
    }

    uint32_t* Qw = (uint32_t*)g_Qh;
    uint32_t* Kw = (uint32_t*)g_Kh;
    const int nb = mA >> 12, ii = mA & 4095;
#pragma unroll
    for (int nt = 0; nt < 12; nt++) {
        const int n0 = h * 96 + nt * 8 + 2 * q;
        if (n0 < 64) {
            Qw[(size_t)mA * 32 + (n0 >> 1)]       = packf16(acc[nt][0], acc[nt][1]);
            Qw[(size_t)(mA + 8) * 32 + (n0 >> 1)] = packf16(acc[nt][2], acc[nt][3]);
        } else if (n0 < 128) {
            const int k0 = n0 - 64;
            Kw[(size_t)mA * 32 + (k0 >> 1)]       = packf16(acc[nt][0], acc[nt][1]);
            Kw[(size_t)(mA + 8) * 32 + (k0 >> 1)] = packf16(acc[nt][2], acc[nt][3]);
        } else {
            const int c = n0 - 128;
            g_Vth[((size_t)nb * 64 + c) * HW + ii]          = __float2half(acc[nt][0]);
            g_Vth[((size_t)nb * 64 + c + 1) * HW + ii]      = __float2half(acc[nt][1]);
            g_Vth[((size_t)nb * 64 + c) * HW + ii + 8]      = __float2half(acc[nt][2]);
            g_Vth[((size_t)nb * 64 + c + 1) * HW + ii + 8]  = __float2half(acc[nt][3]);
        }
    }
}

// ---------------------------------------------------------------------------
// 3a) mom: per 128-j chunk, partial u = sum q and M = sum q q^T (fp32, SIMT).
//     Thread t owns M entries [32t, 32t+32): a = t>>1, b = (t&1)*32 .. +31.
// ---------------------------------------------------------------------------
__global__ __launch_bounds__(128) void mom_k() {
    __shared__ float sQ[128][72];   // padded rows (16B-aligned)
    const int tid = threadIdx.x;
    const int j0 = blockIdx.x * 128, n = blockIdx.y;

    const uint32_t* Qg = (const uint32_t*)g_Qh + ((size_t)n * HW + j0) * 32;
    for (int t = tid; t < 4096; t += 128) {
        const int row = t >> 5, c = t & 31;
        const float2 v = unpackh2(Qg[row * 32 + c]);
        sQ[row][2 * c]     = v.x;
        sQ[row][2 * c + 1] = v.y;
    }
    __syncthreads();

    const int a = tid >> 1, bb = (tid & 1) * 32;
    float macc[32];
#pragma unroll
    for (int p = 0; p < 32; p++) macc[p] = 0.f;
    float uacc = 0.f;

#pragma unroll 2
    for (int j = 0; j < 128; j++) {
        const float qa = sQ[j][a];
        const float4* qb = (const float4*)&sQ[j][bb];
#pragma unroll
        for (int p = 0; p < 8; p++) {
            const float4 v = qb[p];
            macc[4 * p]     = fmaf(qa, v.x, macc[4 * p]);
            macc[4 * p + 1] = fmaf(qa, v.y, macc[4 * p + 1]);
            macc[4 * p + 2] = fmaf(qa, v.z, macc[4 * p + 2]);
            macc[4 * p + 3] = fmaf(qa, v.w, macc[4 * p + 3]);
        }
        if (tid < 64) uacc += sQ[j][tid];
    }

    float4* Mp = (float4*)(g_Mp + ((size_t)blockIdx.x * MAXN + n) * 4096 + tid * 32);
#pragma unroll
    for (int p = 0; p < 8; p++)
        Mp[p] = make_float4(macc[4 * p], macc[4 * p + 1], macc[4 * p + 2], macc[4 * p + 3]);
    if (tid < 64) g_up[((size_t)blockIdx.x * MAXN + n) * 64 + tid] = uacc;
}

// ---------------------------------------------------------------------------
// 3b) taylor + scaleV (fused): reduce M/u partials in-block, compute
//     rowsum_i = 4096 + LN2*(Kt_i.u) + 0.5*LN2^2*(Kt_i^T M Kt_i), then scale
//     this block's V columns in place: V'' = V * 64 / rowsum.
// ---------------------------------------------------------------------------
__global__ __launch_bounds__(128) void taylor_k() {
    __shared__ float sM[4096];
    __shared__ float su[64];
    __shared__ float sInv[128];
    const int tid = threadIdx.x;
    const int i0 = blockIdx.x * 128, n = blockIdx.y;
    const int i = i0 + tid;

    // reduce the 32 M partials (fixed order, L2-resident)
    for (int t = tid; t < 4096; t += 128) {
        float s = 0.f;
#pragma unroll 8
        for (int p = 0; p < 32; p++) s += g_Mp[((size_t)p * MAXN + n) * 4096 + t];
        sM[t] = s;
    }
    if (tid < 64) {
        float s = 0.f;
#pragma unroll 8
        for (int p = 0; p < 32; p++) s += g_up[((size_t)p * MAXN + n) * 64 + tid];
        su[tid] = s;
    }
    __syncthreads();

    float k[64];
    const uint32_t* kg = (const uint32_t*)g_Kh + ((size_t)n * HW + i) * 32;
#pragma unroll
    for (int c = 0; c < 32; c++) {
        const float2 v = unpackh2(kg[c]);
        k[2 * c] = v.x; k[2 * c + 1] = v.y;
    }

    float t1 = 0.f;
#pragma unroll
    for (int d = 0; d < 64; d++) t1 = fmaf(k[d], su[d], t1);

    float quad = 0.f;
    const float4* M4 = (const float4*)sM;
#pragma unroll 4
    for (int d = 0; d < 64; d++) {
        float r0 = 0.f, r1 = 0.f, r2 = 0.f, r3 = 0.f;
#pragma unroll
        for (int e4 = 0; e4 < 16; e4 += 4) {
            const float4 m0 = M4[d * 16 + e4];
            const float4 m1 = M4[d * 16 + e4 + 1];
            const float4 m2 = M4[d * 16 + e4 + 2];
            const float4 m3 = M4[d * 16 + e4 + 3];
            r0 = fmaf(m0.x, k[4 * e4],      fmaf(m0.y, k[4 * e4 + 1],  fmaf(m0.z, k[4 * e4 + 2],  fmaf(m0.w, k[4 * e4 + 3], r0))));
            r1 = fmaf(m1.x, k[4 * e4 + 4],  fmaf(m1.y, k[4 * e4 + 5],  fmaf(m1.z, k[4 * e4 + 6],  fmaf(m1.w, k[4 * e4 + 7], r1))));
            r2 = fmaf(m2.x, k[4 * e4 + 8],  fmaf(m2.y, k[4 * e4 + 9],  fmaf(m2.z, k[4 * e4 + 10], fmaf(m2.w, k[4 * e4 + 11], r2))));
            r3 = fmaf(m3.x, k[4 * e4 + 12], fmaf(m3.y, k[4 * e4 + 13], fmaf(m3.z, k[4 * e4 + 14], fmaf(m3.w, k[4 * e4 + 15], r3))));
        }
        quad = fmaf((r0 + r1) + (r2 + r3), k[d], quad);
    }

    sInv[tid] = 64.0f / (4096.0f + LN2 * t1 + 0.5f * LN2 * LN2 * quad);
    __syncthreads();

    // scale this block's V columns in place: V[c][i0..i0+127] *= inv_i
    __half2* V2 = (__half2*)g_Vth + (size_t)n * CR * (HW / 2) + (i0 >> 1);
    for (int t = tid; t < 4096; t += 128) {
        const int c = t >> 6, i2 = t & 63;
        const size_t o = (size_t)c * (HW / 2) + i2;
        const float2 v = __half22float2(V2[o]);
        V2[o] = __floats2half2_rn(v.x * sInv[2 * i2], v.y * sInv[2 * i2 + 1]);
    }
}

// ---------------------------------------------------------------------------
// 4) Pass B over an i-quarter (R10/R13-proven core + coalesced f16 epilogue)
// ---------------------------------------------------------------------------
__global__ __launch_bounds__(128, 4) void attn_k() {
    __shared__ uint32_t sK[2][64 * 36];
    __shared__ uint32_t sVt[2][64 * 36];
    const int tid = threadIdx.x, lane = tid & 31, w = tid >> 5;
    const int r = lane >> 2, q = lane & 3;
    const int j0 = blockIdx.x * 128, ih = blockIdx.y, n = blockIdx.z;

    uint32_t aq[2][4][4];
    const uint32_t* Qg = (const uint32_t*)g_Qh + (size_t)n * HW * 32;
#pragma unroll
    for (int s = 0; s < 2; s++)
#pragma unroll
        for (int ks = 0; ks < 4; ks++) {
            const uint32_t* qr = Qg + (size_t)(j0 + 32 * w + 16 * s + r) * 32 + ks * 8 + q;
            aq[s][ks][0] = qr[0]; aq[s][ks][1] = qr[256]; aq[s][ks][2] = qr[4]; aq[s][ks][3] = qr[260];
        }
    const uint32_t* Kg = (const uint32_t*)g_Kh + (size_t)n * HW * 32;
    const uint32_t* Vg = (const uint32_t*)g_Vth + (size_t)n * CR * (HW / 2);

    const uint32_t skb[2] = {s2u(sK[0]),  s2u(sK[1])};
    const uint32_t svb[2] = {s2u(sVt[0]), s2u(sVt[1])};
    const uint32_t loff1 = (lane & 7) * 144 + (lane >> 3) * 16;
    const uint32_t loff2 = (lane & 7) * 144 + ((lane >> 3) & 1) * 16 + (lane >> 4) * 1152;

    auto issue = [&](int ch, int buf) {
        const int i0 = ih * 1024 + ch * 64;
#pragma unroll
        for (int t = tid; t < 512; t += 128) {
            const int row = t >> 3, c4 = (t & 7) * 4;
            cpasync16(skb[buf] + row * 144 + c4 * 4, Kg + (size_t)(i0 + row) * 32 + c4);
            cpasync16(svb[buf] + row * 144 + c4 * 4, Vg + (size_t)row * 2048 + (i0 >> 1) + c4);
        }
    };

    uint32_t acc[2][8][2];
#pragma unroll
    for (int s = 0; s < 2; s++)
#pragma unroll
        for (int ct = 0; ct < 8; ct++)
            acc[s][ct][0] = acc[s][ct][1] = 0u;

    issue(0, 0); cpcommit();
    for (int ch = 0; ch < 16; ch++) {
        if (ch < 15) { issue(ch + 1, (ch + 1) & 1); cpcommit(); cpwait<1>(); }
        else cpwait<0>();
        __syncthreads();
        const int buf = ch & 1;
        const uint32_t kb = skb[buf], vb = svb[buf];

#pragma unroll
        for (int ks2 = 0; ks2 < 4; ks2++) {
            uint32_t ap[2][4];
#pragma unroll
            for (int half = 0; half < 2; half++) {
                const int nt = 2 * ks2 + half;
                uint32_t b00, b10, b01, b11, b02, b12, b03, b13;
                ldsm_x4(b00, b10, b01, b11, kb + nt * 1152 + loff1);
                ldsm_x4(b02, b12, b03, b13, kb + nt * 1152 + 64 + loff1);
#pragma unroll
                for (int s = 0; s < 2; s++) {
                    uint32_t d0 = 0u, d1 = 0u;
                    mma16816h(d0, d1, aq[s][0][0], aq[s][0][1], aq[s][0][2], aq[s][0][3], b00, b10);
                    mma16816h(d0, d1, aq[s][1][0], aq[s][1][1], aq[s][1][2], aq[s][1][3], b01, b11);
                    mma16816h(d0, d1, aq[s][2][0], aq[s][2][1], aq[s][2][2], aq[s][2][3], b02, b12);
                    mma16816h(d0, d1, aq[s][3][0], aq[s][3][1], aq[s][3][2], aq[s][3][3], b03, b13);
                    ap[s][half]     = ex2h2(d0);
                    ap[s][2 + half] = ex2h2(d1);
                }
            }
#pragma unroll
            for (int ctp = 0; ctp < 4; ctp++) {
                uint32_t v0, v1, v2, v3;
                ldsm_x4(v0, v1, v2, v3, vb + ctp * 2304 + ks2 * 32 + loff2);
#pragma unroll
                for (int s = 0; s < 2; s++) {
                    mma16816h(acc[s][2 * ctp][0], acc[s][2 * ctp][1],
                              ap[s][0], ap[s][2], ap[s][1], ap[s][3], v0, v1);
                    mma16816h(acc[s][2 * ctp + 1][0], acc[s][2 * ctp + 1][1],
                              ap[s][0], ap[s][2], ap[s][1], ap[s][3], v2, v3);
                }
            }
        }
        __syncthreads();
    }

    uint32_t* A2 = (uint32_t*)(g_attph[ih] + ((size_t)n * HW + j0) * CR);
#pragma unroll
    for (int s = 0; s < 2; s++) {
        const int jl = 32 * w + 16 * s + r;
#pragma unroll
        for (int ct = 0; ct < 8; ct++) {
            A2[(size_t)jl * 32 + ct * 4 + q]       = acc[s][ct][0];
            A2[(size_t)(jl + 8) * 32 + ct * 4 + q] = acc[s][ct][1];
        }
    }
}

// ---------------------------------------------------------------------------
// 5) Final (R13-proven): coalesced half2 partial reads; Wa f16 in registers.
// ---------------------------------------------------------------------------
__global__ __launch_bounds__(256) void final_k(const float* __restrict__ G,
                                               const float* __restrict__ ba,
                                               float* __restrict__ out) {
    __shared__ float sa[64][68];
    const int b = blockIdx.x;
    const int n = b >> 6, w = b & 63;
    const int tid = threadIdx.x;

    const uint32_t* P0 = (const uint32_t*)(g_attph[0] + ((size_t)n * HW + w * 64) * CR);
    const uint32_t* P1 = (const uint32_t*)(g_attph[1] + ((size_t)n * HW + w * 64) * CR);
    const uint32_t* P2 = (const uint32_t*)(g_attph[2] + ((size_t)n * HW + w * 64) * CR);
    const uint32_t* P3 = (const uint32_t*)(g_attph[3] + ((size_t)n * HW + w * 64) * CR);
    for (int idx = tid; idx < 2048; idx += 256) {
        const int cr = idx >> 5, h2 = idx & 31;
        const size_t o = (size_t)cr * 32 + h2;
        const float2 v0 = unpackh2(P0[o]);
        const float2 v1 = unpackh2(P1[o]);
        const float2 v2 = unpackh2(P2[o]);
        const float2 v3 = unpackh2(P3[o]);
        sa[2 * h2][cr]     = v0.x + v1.x + v2.x + v3.x;
        sa[2 * h2 + 1][cr] = v0.y + v1.y + v2.y + v3.y;
    }
    __syncthreads();

    float wa[64];
#pragma unroll
    for (int cr = 0; cr < 64; cr++) wa[cr] = __half2float(g_Wah[cr * CIN + tid]);
    const float vba = ba[tid];

    size_t gidx = ((size_t)n * HW + w) * CIN + tid;
    for (int h = 0; h < 64; h++) {
        float acc = vba;
        const float4* row = (const float4*)sa[h];
#pragma unroll
        for (int k = 0; k < 16; k++) {
            const float4 v = row[k];
            acc = fmaf(v.x, wa[4 * k],     acc);
            acc = fmaf(v.y, wa[4 * k + 1], acc);
            acc = fmaf(v.z, wa[4 * k + 2], acc);
            acc = fmaf(v.w, wa[4 * k + 3], acc);
        }
        const float g = G[gidx];
        out[gidx] = fmaf(g, acc, g);
        gidx += (size_t)64 * CIN;
    }
}

// ---------------------------------------------------------------------------
extern "C" void kernel_launch(void* const* d_in, const int* in_sizes, int n_in,
                              void* d_out, int out_size) {
    const float* X   = (const float*)d_in[0];
    const float* G   = (const float*)d_in[1];
    const float* dwq = (const float*)d_in[2];
    const float* pwq = (const float*)d_in[3];
    const float* bq  = (const float*)d_in[4];
    const float* dwk = (const float*)d_in[5];
    const float* pwk = (const float*)d_in[6];
    const float* bk  = (const float*)d_in[7];
    const float* dwv = (const float*)d_in[8];
    const float* pwv = (const float*)d_in[9];
    const float* bv  = (const float*)d_in[10];
    const float* dwa = (const float*)d_in[11];
    const float* pwa = (const float*)d_in[12];
    const float* ba  = (const float*)d_in[13];
    float* out = (float*)d_out;

    const int N = in_sizes[0] / (HW * CIN);   // 4

    fold_k<<<96, 256>>>(dwq, pwq, bq, dwk, pwk, bk, dwv, pwv, bv, dwa, pwa);
    proj_k<<<dim3((N * HW) / 128, 2), 256>>>(X);
    mom_k<<<dim3(HW / 128, N), 128>>>();
    taylor_k<<<dim3(HW / 128, N), 128>>>();
    attn_k<<<dim3(HW / 128, 4, N), 128>>>();
    final_k<<<N * 64, 256>>>(G, ba, out);
}

// round 16
// speedup vs baseline: 1.4221x; 1.4221x over previous
#include <cuda_runtime.h>
#include <cuda_fp16.h>
#include <stdint.h>

// Shapes fixed by the problem: N=4, H=W=64, C_in=256, C_red=64
constexpr int HW   = 4096;
constexpr int CIN  = 256;
constexpr int CR   = 64;
constexpr int MAXN = 4;
constexpr float LOG2E = 1.4426950408889634f;

// ---------------- device scratch (allocation-free) ----------------
__device__ __half g_Wah[CR * CIN];                        // f16 [cr][cout], pre-scaled by 1/64
__device__ uint32_t g_Wfrag[2 * 12288];                   // qkv weights in B-fragment order (f16x2)
__device__ float g_b192[192];
__device__ __half g_Qh[(size_t)MAXN * HW * CR];           // [n*HW + j][c]
__device__ __half g_Kh[(size_t)MAXN * HW * CR];           // [n*HW + i][c], pre-scaled by log2e
__device__ __half g_Vth[(size_t)MAXN * CR * HW];          // [n][c][i] -> scaled to V''=V*64/rowsum
__device__ float g_part[4][MAXN * HW];                    // rowsum partials (j-quarters)
__device__ __half g_attph[4][(size_t)MAXN * HW * CR];     // att partials [ih][n][j][c] (64x att)

// ---------------- helpers ----------------
__device__ __forceinline__ uint32_t s2u(const void* p) {
    return (uint32_t)__cvta_generic_to_shared(p);
}
__device__ __forceinline__ void mma16816(float& c0, float& c1, float& c2, float& c3,
                                         uint32_t a0, uint32_t a1, uint32_t a2, uint32_t a3,
                                         uint32_t b0, uint32_t b1) {
    asm volatile("mma.sync.aligned.m16n8k16.row.col.f32.f16.f16.f32 "
                 "{%0,%1,%2,%3}, {%4,%5,%6,%7}, {%8,%9}, {%0,%1,%2,%3};"
                 : "+f"(c0), "+f"(c1), "+f"(c2), "+f"(c3)
                 : "r"(a0), "r"(a1), "r"(a2), "r"(a3), "r"(b0), "r"(b1));
}
__device__ __forceinline__ void mma16816h(uint32_t& d0, uint32_t& d1,
                                          uint32_t a0, uint32_t a1, uint32_t a2, uint32_t a3,
                                          uint32_t b0, uint32_t b1) {
    asm volatile("mma.sync.aligned.m16n8k16.row.col.f16.f16.f16.f16 "
                 "{%0,%1}, {%2,%3,%4,%5}, {%6,%7}, {%0,%1};"
                 : "+r"(d0), "+r"(d1)
                 : "r"(a0), "r"(a1), "r"(a2), "r"(a3), "r"(b0), "r"(b1));
}
__device__ __forceinline__ uint32_t packf16(float lo, float hi) {
    uint32_t d;
    asm("cvt.rn.f16x2.f32 %0, %1, %2;" : "=r"(d) : "f"(hi), "f"(lo));
    return d;
}
__device__ __forceinline__ float2 unpackh2(uint32_t u) {
    __half2 h = *reinterpret_cast<__half2*>(&u);
    return __half22float2(h);
}
__device__ __forceinline__ uint32_t ex2h2(uint32_t x) {
    uint32_t d;
    asm("ex2.approx.f16x2 %0, %1;" : "=r"(d) : "r"(x));
    return d;
}
__device__ __forceinline__ float fex2(float x) {
    float d;
    asm("ex2.approx.ftz.f32 %0, %1;" : "=f"(d) : "f"(x));
    return d;
}
__device__ __forceinline__ void cpasync16(uint32_t saddr, const void* g) {
    asm volatile("cp.async.ca.shared.global [%0], [%1], 16;" :: "r"(saddr), "l"(g));
}
__device__ __forceinline__ void cpcommit() { asm volatile("cp.async.commit_group;"); }
template<int N> __device__ __forceinline__ void cpwait() {
    asm volatile("cp.async.wait_group %0;" :: "n"(N));
}
__device__ __forceinline__ void ldsm_x4(uint32_t& r0, uint32_t& r1, uint32_t& r2, uint32_t& r3,
                                        uint32_t addr) {
    asm volatile("ldmatrix.sync.aligned.m8n8.x4.shared.b16 {%0,%1,%2,%3}, [%4];"
                 : "=r"(r0), "=r"(r1), "=r"(r2), "=r"(r3) : "r"(addr));
}

// ---------------------------------------------------------------------------
// 1) fold: Wa (f16, /64), bias, qkv weights in B-frag order; K scaled log2e
// ---------------------------------------------------------------------------
__global__ void fold_k(const float* __restrict__ dwq, const float* __restrict__ pwq,
                       const float* __restrict__ bq,
                       const float* __restrict__ dwk, const float* __restrict__ pwk,
                       const float* __restrict__ bk,
                       const float* __restrict__ dwv, const float* __restrict__ pwv,
                       const float* __restrict__ bv,
                       const float* __restrict__ dwa, const float* __restrict__ pwa) {
    const int idx = blockIdx.x * 256 + threadIdx.x;   // 0..24575
    if (idx < 16384) {
        const int cr = idx >> 8;
        g_Wah[idx] = __float2half(dwa[cr] * pwa[idx] * 0.015625f);   // 1/64 compensates V''
    }
    if (idx < 192)
        g_b192[idx] = (idx < 64) ? bq[idx]
                    : (idx < 128 ? bk[idx - 64] * LOG2E : bv[idx - 128]);

    const int nn = idx >> 7;       // output unit 0..191
    const int p  = idx & 127;      // c-pair 0..127
    const int c0 = 2 * p, c1 = 2 * p + 1;
    float w0, w1;
    if (nn < 64)       { w0 = dwq[c0] * pwq[c0 * 64 + nn];        w1 = dwq[c1] * pwq[c1 * 64 + nn]; }
    else if (nn < 128) { const int m = nn - 64;
                         w0 = dwk[c0] * pwk[c0 * 64 + m] * LOG2E;
                         w1 = dwk[c1] * pwk[c1 * 64 + m] * LOG2E; }
    else               { const int m = nn - 128; w0 = dwv[c0] * pwv[c0 * 64 + m]; w1 = dwv[c1] * pwv[c1 * 64 + m]; }
    const int h = nn / 96, nl = nn % 96, nt = nl >> 3, r = nl & 7;
    const int ks = p >> 3, rem = p & 7, q = rem & 3, slot = rem >> 2;
    g_Wfrag[(((h * 12 + nt) * 16 + ks) * 32 + r * 4 + q) * 2 + slot] = packf16(w0, w1);
}

// ---------------------------------------------------------------------------
// 2) QKV projection via mma.sync (proven R6/R10)
// ---------------------------------------------------------------------------
__global__ __launch_bounds__(256) void proj_k(const float* __restrict__ X) {
    __shared__ uint32_t sW[12288];   // 48 KB
    const int tid = threadIdx.x, lane = tid & 31, w = tid >> 5;
    const int r = lane >> 2, q = lane & 3;
    const int m0 = blockIdx.x * 128, h = blockIdx.y;

    const uint32_t swb = s2u(sW);
    const uint32_t* Wsrc = g_Wfrag + h * 12288;
    for (int t = tid; t < 3072; t += 256) cpasync16(swb + t * 16, Wsrc + t * 4);
    cpcommit(); cpwait<0>(); __syncthreads();

    float acc[12][4];
#pragma unroll
    for (int nt = 0; nt < 12; nt++) {
        const int n0 = h * 96 + nt * 8 + 2 * q;
        const float b0 = g_b192[n0], b1 = g_b192[n0 + 1];
        acc[nt][0] = b0; acc[nt][1] = b1; acc[nt][2] = b0; acc[nt][3] = b1;
    }

    const int mA = m0 + 16 * w + r;
    const float2* X2 = (const float2*)X;
    const uint2* sW2 = (const uint2*)sW;
#pragma unroll 4
    for (int ks = 0; ks < 16; ks++) {
        const float2 u0 = X2[(size_t)mA * 128 + ks * 8 + q];
        const float2 u1 = X2[(size_t)(mA + 8) * 128 + ks * 8 + q];
        const float2 u2 = X2[(size_t)mA * 128 + ks * 8 + q + 4];
        const float2 u3 = X2[(size_t)(mA + 8) * 128 + ks * 8 + q + 4];
        const uint32_t a0 = packf16(u0.x, u0.y);
        const uint32_t a1 = packf16(u1.x, u1.y);
        const uint32_t a2 = packf16(u2.x, u2.y);
        const uint32_t a3 = packf16(u3.x, u3.y);
#pragma unroll
        for (int nt = 0; nt < 12; nt++) {
            const uint2 b = sW2[(nt * 16 + ks) * 32 + lane];
            mma16816(acc[nt][0], acc[nt][1], acc[nt][2], acc[nt][3], a0, a1, a2, a3, b.x, b.y);
        }
    }

    uint32_t* Qw = (uint32_t*)g_Qh;
    uint32_t* Kw = (uint32_t*)g_Kh;
    const int nb = mA >> 12, ii = mA & 4095;
#pragma unroll
    for (int nt = 0; nt < 12; nt++) {
        const int n0 = h * 96 + nt * 8 + 2 * q;
        if (n0 < 64) {
            Qw[(size_t)mA * 32 + (n0 >> 1)]       = packf16(acc[nt][0], acc[nt][1]);
            Qw[(size_t)(mA + 8) * 32 + (n0 >> 1)] = packf16(acc[nt][2], acc[nt][3]);
        } else if (n0 < 128) {
            const int k0 = n0 - 64;
            Kw[(size_t)mA * 32 + (k0 >> 1)]       = packf16(acc[nt][0], acc[nt][1]);
            Kw[(size_t)(mA + 8) * 32 + (k0 >> 1)] = packf16(acc[nt][2], acc[nt][3]);
        } else {
            const int c = n0 - 128;
            g_Vth[((size_t)nb * 64 + c) * HW + ii]          = __float2half(acc[nt][0]);
            g_Vth[((size_t)nb * 64 + c + 1) * HW + ii]      = __float2half(acc[nt][1]);
            g_Vth[((size_t)nb * 64 + c) * HW + ii + 8]      = __float2half(acc[nt][2]);
            g_Vth[((size_t)nb * 64 + c + 1) * HW + ii + 8]  = __float2half(acc[nt][3]);
        }
    }
}

// ---------------------------------------------------------------------------
// 3) Pass A: rowsum partials (R10/R13-proven). S' = S*log2e -> ex2.
// ---------------------------------------------------------------------------
__global__ __launch_bounds__(128, 4) void rowsum_k() {
    __shared__ uint32_t sQ[2][128 * 36];
    const int tid = threadIdx.x, lane = tid & 31, w = tid >> 5;
    const int r = lane >> 2, q = lane & 3;
    const int i0 = blockIdx.x * 128, jq = blockIdx.y, n = blockIdx.z;

    uint32_t a[2][4][4];
    const uint32_t* Kg = (const uint32_t*)g_Kh + (size_t)n * HW * 32;
#pragma unroll
    for (int s = 0; s < 2; s++)
#pragma unroll
        for (int ks = 0; ks < 4; ks++) {
            const uint32_t* kr = Kg + (size_t)(i0 + 32 * w + 16 * s + r) * 32 + ks * 8 + q;
            a[s][ks][0] = kr[0]; a[s][ks][1] = kr[256]; a[s][ks][2] = kr[4]; a[s][ks][3] = kr[260];
        }
    const uint32_t* Qg = (const uint32_t*)g_Qh + ((size_t)n * HW + jq * 1024) * 32;
    const uint32_t sqb0 = s2u(sQ[0]), sqb1 = s2u(sQ[1]);
    const uint32_t loff = (lane & 7) * 144 + (lane >> 3) * 16;

    auto issue = [&](int ch, uint32_t base) {
#pragma unroll
        for (int t = tid; t < 1024; t += 128) {
            const int row = t >> 3, c4 = (t & 7) * 4;
            cpasync16(base + row * 144 + c4 * 4, Qg + (size_t)(ch * 128 + row) * 32 + c4);
        }
    };
    issue(0, sqb0); cpcommit();

    float sA[2] = {0.f, 0.f}, sB[2] = {0.f, 0.f};
    for (int ch = 0; ch < 8; ch++) {
        if (ch < 7) { issue(ch + 1, (ch & 1) ? sqb0 : sqb1); cpcommit(); cpwait<1>(); }
        else cpwait<0>();
        __syncthreads();
        const uint32_t base = (ch & 1) ? sqb1 : sqb0;
#pragma unroll 4
        for (int nt = 0; nt < 16; nt++) {
            uint32_t b00, b10, b01, b11, b02, b12, b03, b13;
            ldsm_x4(b00, b10, b01, b11, base + nt * 1152 + loff);
            ldsm_x4(b02, b12, b03, b13, base + nt * 1152 + 64 + loff);
#pragma unroll
            for (int s = 0; s < 2; s++) {
                uint32_t d0 = 0u, d1 = 0u;
                mma16816h(d0, d1, a[s][0][0], a[s][0][1], a[s][0][2], a[s][0][3], b00, b10);
                mma16816h(d0, d1, a[s][1][0], a[s][1][1], a[s][1][2], a[s][1][3], b01, b11);
                mma16816h(d0, d1, a[s][2][0], a[s][2][1], a[s][2][2], a[s][2][3], b02, b12);
                mma16816h(d0, d1, a[s][3][0], a[s][3][1], a[s][3][2], a[s][3][3], b03, b13);
                const float2 f0 = unpackh2(d0), f1 = unpackh2(d1);
                sA[s] += fex2(f0.x) + fex2(f0.y);
                sB[s] += fex2(f1.x) + fex2(f1.y);
            }
        }
        __syncthreads();
    }
#pragma unroll
    for (int s = 0; s < 2; s++) {
        float va = sA[s], vb = sB[s];
        va += __shfl_xor_sync(0xffffffffu, va, 1);
        va += __shfl_xor_sync(0xffffffffu, va, 2);
        vb += __shfl_xor_sync(0xffffffffu, vb, 1);
        vb += __shfl_xor_sync(0xffffffffu, vb, 2);
        if (q == 0) {
            g_part[jq][n * HW + i0 + 32 * w + 16 * s + r]     = va;
            g_part[jq][n * HW + i0 + 32 * w + 16 * s + r + 8] = vb;
        }
    }
}

// ---------------------------------------------------------------------------
// 3b) scale V in place: V''[c,i] = V[c,i] * 64 / rowsum_i  (R10/R13-proven)
// ---------------------------------------------------------------------------
__global__ void scalev_k() {
    const int idx = blockIdx.x * 256 + threadIdx.x;   // over half2 elements
    const int i2 = idx % (HW / 2);
    const int nc = idx / (HW / 2);
    const int n = nc >> 6;
    const int gi = n * HW + i2 * 2;
    const float inv0 = 64.0f / (g_part[0][gi] + g_part[1][gi] + g_part[2][gi] + g_part[3][gi]);
    const float inv1 = 64.0f / (g_part[0][gi + 1] + g_part[1][gi + 1] + g_part[2][gi + 1] + g_part[3][gi + 1]);
    __half2* V2 = (__half2*)g_Vth;
    const float2 v = __half22float2(V2[(size_t)nc * (HW / 2) + i2]);
    V2[(size_t)nc * (HW / 2) + i2] = __floats2half2_rn(v.x * inv0, v.y * inv1);
}

// ---------------------------------------------------------------------------
// 4) Pass B over an i-quarter (R13-proven core) with a 3-stage cp.async
//    pipeline (two chunk-loads in flight) + coalesced f16 [j][c] epilogue.
// ---------------------------------------------------------------------------
__global__ __launch_bounds__(128, 4) void attn_k() {
    __shared__ uint32_t sK[3][64 * 36];
    __shared__ uint32_t sVt[3][64 * 36];
    const int tid = threadIdx.x, lane = tid & 31, w = tid >> 5;
    const int r = lane >> 2, q = lane & 3;
    const int j0 = blockIdx.x * 128, ih = blockIdx.y, n = blockIdx.z;

    uint32_t aq[2][4][4];
    const uint32_t* Qg = (const uint32_t*)g_Qh + (size_t)n * HW * 32;
#pragma unroll
    for (int s = 0; s < 2; s++)
#pragma unroll
        for (int ks = 0; ks < 4; ks++) {
            const uint32_t* qr = Qg + (size_t)(j0 + 32 * w + 16 * s + r) * 32 + ks * 8 + q;
            aq[s][ks][0] = qr[0]; aq[s][ks][1] = qr[256]; aq[s][ks][2] = qr[4]; aq[s][ks][3] = qr[260];
        }
    const uint32_t* Kg = (const uint32_t*)g_Kh + (size_t)n * HW * 32;
    const uint32_t* Vg = (const uint32_t*)g_Vth + (size_t)n * CR * (HW / 2);

    const uint32_t skb[3] = {s2u(sK[0]),  s2u(sK[1]),  s2u(sK[2])};
    const uint32_t svb[3] = {s2u(sVt[0]), s2u(sVt[1]), s2u(sVt[2])};
    const uint32_t loff1 = (lane & 7) * 144 + (lane >> 3) * 16;
    const uint32_t loff2 = (lane & 7) * 144 + ((lane >> 3) & 1) * 16 + (lane >> 4) * 1152;

    auto issue = [&](int ch, int buf) {
        const int i0 = ih * 1024 + ch * 64;
#pragma unroll
        for (int t = tid; t < 512; t += 128) {
            const int row = t >> 3, c4 = (t & 7) * 4;
            cpasync16(skb[buf] + row * 144 + c4 * 4, Kg + (size_t)(i0 + row) * 32 + c4);
            cpasync16(svb[buf] + row * 144 + c4 * 4, Vg + (size_t)row * 2048 + (i0 >> 1) + c4);
        }
    };

    uint32_t acc[2][8][2];
#pragma unroll
    for (int s = 0; s < 2; s++)
#pragma unroll
        for (int ct = 0; ct < 8; ct++)
            acc[s][ct][0] = acc[s][ct][1] = 0u;

    issue(0, 0); cpcommit();
    issue(1, 1); cpcommit();
    for (int ch = 0; ch < 16; ch++) {
        if (ch < 15) cpwait<1>();   // group ch complete; ch+1 may be in flight
        else cpwait<0>();
        __syncthreads();            // also fences buffer (ch+2)%3 reads from iter ch-1
        const int buf = ch % 3;
        const uint32_t kb = skb[buf], vb = svb[buf];

#pragma unroll
        for (int ks2 = 0; ks2 < 4; ks2++) {
            uint32_t ap[2][4];
#pragma unroll
            for (int half = 0; half < 2; half++) {
                const int nt = 2 * ks2 + half;
                uint32_t b00, b10, b01, b11, b02, b12, b03, b13;
                ldsm_x4(b00, b10, b01, b11, kb + nt * 1152 + loff1);
                ldsm_x4(b02, b12, b03, b13, kb + nt * 1152 + 64 + loff1);
#pragma unroll
                for (int s = 0; s < 2; s++) {
                    uint32_t d0 = 0u, d1 = 0u;
                    mma16816h(d0, d1, aq[s][0][0], aq[s][0][1], aq[s][0][2], aq[s][0][3], b00, b10);
                    mma16816h(d0, d1, aq[s][1][0], aq[s][1][1], aq[s][1][2], aq[s][1][3], b01, b11);
                    mma16816h(d0, d1, aq[s][2][0], aq[s][2][1], aq[s][2][2], aq[s][2][3], b02, b12);
                    mma16816h(d0, d1, aq[s][3][0], aq[s][3][1], aq[s][3][2], aq[s][3][3], b03, b13);
                    ap[s][half]     = ex2h2(d0);
                    ap[s][2 + half] = ex2h2(d1);
                }
            }
#pragma unroll
            for (int ctp = 0; ctp < 4; ctp++) {
                uint32_t v0, v1, v2, v3;
                ldsm_x4(v0, v1, v2, v3, vb + ctp * 2304 + ks2 * 32 + loff2);
#pragma unroll
                for (int s = 0; s < 2; s++) {
                    mma16816h(acc[s][2 * ctp][0], acc[s][2 * ctp][1],
                              ap[s][0], ap[s][2], ap[s][1], ap[s][3], v0, v1);
                    mma16816h(acc[s][2 * ctp + 1][0], acc[s][2 * ctp + 1][1],
                              ap[s][0], ap[s][2], ap[s][1], ap[s][3], v2, v3);
                }
            }
        }
        if (ch < 14) { issue(ch + 2, (ch + 2) % 3); cpcommit(); }
    }

    uint32_t* A2 = (uint32_t*)(g_attph[ih] + ((size_t)n * HW + j0) * CR);
#pragma unroll
    for (int s = 0; s < 2; s++) {
        const int jl = 32 * w + 16 * s + r;
#pragma unroll
        for (int ct = 0; ct < 8; ct++) {
            A2[(size_t)jl * 32 + ct * 4 + q]       = acc[s][ct][0];
            A2[(size_t)(jl + 8) * 32 + ct * 4 + q] = acc[s][ct][1];
        }
    }
}

// ---------------------------------------------------------------------------
// 5) Final (R13-proven): coalesced half2 partial reads; Wa f16 in registers.
// ---------------------------------------------------------------------------
__global__ __launch_bounds__(256) void final_k(const float* __restrict__ G,
                                               const float* __restrict__ ba,
                                               float* __restrict__ out) {
    __shared__ float sa[64][68];
    const int b = blockIdx.x;
    const int n = b >> 6, w = b & 63;
    const int tid = threadIdx.x;

    const uint32_t* P0 = (const uint32_t*)(g_attph[0] + ((size_t)n * HW + w * 64) * CR);
    const uint32_t* P1 = (const uint32_t*)(g_attph[1] + ((size_t)n * HW + w * 64) * CR);
    const uint32_t* P2 = (const uint32_t*)(g_attph[2] + ((size_t)n * HW + w * 64) * CR);
    const uint32_t* P3 = (const uint32_t*)(g_attph[3] + ((size_t)n * HW + w * 64) * CR);
    for (int idx = tid; idx < 2048; idx += 256) {
        const int cr = idx >> 5, h2 = idx & 31;
        const size_t o = (size_t)cr * 32 + h2;
        const float2 v0 = unpackh2(P0[o]);
        const float2 v1 = unpackh2(P1[o]);
        const float2 v2 = unpackh2(P2[o]);
        const float2 v3 = unpackh2(P3[o]);
        sa[2 * h2][cr]     = v0.x + v1.x + v2.x + v3.x;
        sa[2 * h2 + 1][cr] = v0.y + v1.y + v2.y + v3.y;
    }
    __syncthreads();

    float wa[64];
#pragma unroll
    for (int cr = 0; cr < 64; cr++) wa[cr] = __half2float(g_Wah[cr * CIN + tid]);
    const float vba = ba[tid];

    size_t gidx = ((size_t)n * HW + w) * CIN + tid;
    for (int h = 0; h < 64; h++) {
        float acc = vba;
        const float4* row = (const float4*)sa[h];
#pragma unroll
        for (int k = 0; k < 16; k++) {
            const float4 v = row[k];
            acc = fmaf(v.x, wa[4 * k],     acc);
            acc = fmaf(v.y, wa[4 * k + 1], acc);
            acc = fmaf(v.z, wa[4 * k + 2], acc);
            acc = fmaf(v.w, wa[4 * k + 3], acc);
        }
        const float g = G[gidx];
        out[gidx] = fmaf(g, acc, g);
        gidx += (size_t)64 * CIN;
    }
}

// ---------------------------------------------------------------------------
extern "C" void kernel_launch(void* const* d_in, const int* in_sizes, int n_in,
                              void* d_out, int out_size) {
    const float* X   = (const float*)d_in[0];
    const float* G   = (const float*)d_in[1];
    const float* dwq = (const float*)d_in[2];
    const float* pwq = (const float*)d_in[3];
    const float* bq  = (const float*)d_in[4];
    const float* dwk = (const float*)d_in[5];
    const float* pwk = (const float*)d_in[6];
    const float* bk  = (const float*)d_in[7];
    const float* dwv = (const float*)d_in[8];
    const float* pwv = (const float*)d_in[9];
    const float* bv  = (const float*)d_in[10];
    const float* dwa = (const float*)d_in[11];
    const float* pwa = (const float*)d_in[12];
    const float* ba  = (const float*)d_in[13];
    float* out = (float*)d_out;

    const int N = in_sizes[0] / (HW * CIN);   // 4

    fold_k<<<96, 256>>>(dwq, pwq, bq, dwk, pwk, bk, dwv, pwv, bv, dwa, pwa);
    proj_k<<<dim3((N * HW) / 128, 2), 256>>>(X);
    rowsum_k<<<dim3(HW / 128, 4, N), 128>>>();
    scalev_k<<<(N * CR * HW / 2) / 256, 256>>>();
    attn_k<<<dim3(HW / 128, 4, N), 128>>>();
    final_k<<<N * 64, 256>>>(G, ba, out);
}

// round 17
// speedup vs baseline: 1.4519x; 1.0210x over previous
#include <cuda_runtime.h>
#include <cuda_fp16.h>
#include <stdint.h>

// Shapes fixed by the problem: N=4, H=W=64, C_in=256, C_red=64
constexpr int HW   = 4096;
constexpr int CIN  = 256;
constexpr int CR   = 64;
constexpr int MAXN = 4;
constexpr float LOG2E = 1.4426950408889634f;

// ---------------- device scratch (allocation-free) ----------------
__device__ __half g_Wah[CR * CIN];                        // f16 [cr][cout], pre-scaled by 1/64
__device__ uint32_t g_Wfrag[2 * 12288];                   // qkv weights in B-fragment order (f16x2)
__device__ float g_b192[192];
__device__ __half g_Qh[(size_t)MAXN * HW * CR];           // [n*HW + j][c]
__device__ __half g_Kh[(size_t)MAXN * HW * CR];           // [n*HW + i][c], pre-scaled by log2e
__device__ __half g_Vth[(size_t)MAXN * CR * HW];          // [n][c][i] (unscaled)
__device__ float g_part[4][MAXN * HW];                    // rowsum partials (j-quarters)
__device__ __half g_attph[4][(size_t)MAXN * HW * CR];     // att partials [ih][n][j][c] (64x att)

// ---------------- helpers ----------------
__device__ __forceinline__ uint32_t s2u(const void* p) {
    return (uint32_t)__cvta_generic_to_shared(p);
}
__device__ __forceinline__ void mma16816(float& c0, float& c1, float& c2, float& c3,
                                         uint32_t a0, uint32_t a1, uint32_t a2, uint32_t a3,
                                         uint32_t b0, uint32_t b1) {
    asm volatile("mma.sync.aligned.m16n8k16.row.col.f32.f16.f16.f32 "
                 "{%0,%1,%2,%3}, {%4,%5,%6,%7}, {%8,%9}, {%0,%1,%2,%3};"
                 : "+f"(c0), "+f"(c1), "+f"(c2), "+f"(c3)
                 : "r"(a0), "r"(a1), "r"(a2), "r"(a3), "r"(b0), "r"(b1));
}
__device__ __forceinline__ void mma16816h(uint32_t& d0, uint32_t& d1,
                                          uint32_t a0, uint32_t a1, uint32_t a2, uint32_t a3,
                                          uint32_t b0, uint32_t b1) {
    asm volatile("mma.sync.aligned.m16n8k16.row.col.f16.f16.f16.f16 "
                 "{%0,%1}, {%2,%3,%4,%5}, {%6,%7}, {%0,%1};"
                 : "+r"(d0), "+r"(d1)
                 : "r"(a0), "r"(a1), "r"(a2), "r"(a3), "r"(b0), "r"(b1));
}
__device__ __forceinline__ uint32_t packf16(float lo, float hi) {
    uint32_t d;
    asm("cvt.rn.f16x2.f32 %0, %1, %2;" : "=r"(d) : "f"(hi), "f"(lo));
    return d;
}
__device__ __forceinline__ float2 unpackh2(uint32_t u) {
    __half2 h = *reinterpret_cast<__half2*>(&u);
    return __half22float2(h);
}
__device__ __forceinline__ uint32_t ex2h2(uint32_t x) {
    uint32_t d;
    asm("ex2.approx.f16x2 %0, %1;" : "=r"(d) : "r"(x));
    return d;
}
__device__ __forceinline__ uint32_t hmul2u(uint32_t a, uint32_t b) {
    uint32_t d;
    asm("mul.rn.f16x2 %0, %1, %2;" : "=r"(d) : "r"(a), "r"(b));
    return d;
}
__device__ __forceinline__ float fex2(float x) {
    float d;
    asm("ex2.approx.ftz.f32 %0, %1;" : "=f"(d) : "f"(x));
    return d;
}
__device__ __forceinline__ void cpasync16(uint32_t saddr, const void* g) {
    asm volatile("cp.async.ca.shared.global [%0], [%1], 16;" :: "r"(saddr), "l"(g));
}
__device__ __forceinline__ void cpcommit() { asm volatile("cp.async.commit_group;"); }
template<int N> __device__ __forceinline__ void cpwait() {
    asm volatile("cp.async.wait_group %0;" :: "n"(N));
}
__device__ __forceinline__ void ldsm_x4(uint32_t& r0, uint32_t& r1, uint32_t& r2, uint32_t& r3,
                                        uint32_t addr) {
    asm volatile("ldmatrix.sync.aligned.m8n8.x4.shared.b16 {%0,%1,%2,%3}, [%4];"
                 : "=r"(r0), "=r"(r1), "=r"(r2), "=r"(r3) : "r"(addr));
}

// ---------------------------------------------------------------------------
// 1) fold: Wa (f16, /64), bias, qkv weights in B-frag order; K scaled log2e
// ---------------------------------------------------------------------------
__global__ void fold_k(const float* __restrict__ dwq, const float* __restrict__ pwq,
                       const float* __restrict__ bq,
                       const float* __restrict__ dwk, const float* __restrict__ pwk,
                       const float* __restrict__ bk,
                       const float* __restrict__ dwv, const float* __restrict__ pwv,
                       const float* __restrict__ bv,
                       const float* __restrict__ dwa, const float* __restrict__ pwa) {
    const int idx = blockIdx.x * 256 + threadIdx.x;   // 0..24575
    if (idx < 16384) {
        const int cr = idx >> 8;
        g_Wah[idx] = __float2half(dwa[cr] * pwa[idx] * 0.015625f);   // 1/64 compensates P'*64
    }
    if (idx < 192)
        g_b192[idx] = (idx < 64) ? bq[idx]
                    : (idx < 128 ? bk[idx - 64] * LOG2E : bv[idx - 128]);

    const int nn = idx >> 7;       // output unit 0..191
    const int p  = idx & 127;      // c-pair 0..127
    const int c0 = 2 * p, c1 = 2 * p + 1;
    float w0, w1;
    if (nn < 64)       { w0 = dwq[c0] * pwq[c0 * 64 + nn];        w1 = dwq[c1] * pwq[c1 * 64 + nn]; }
    else if (nn < 128) { const int m = nn - 64;
                         w0 = dwk[c0] * pwk[c0 * 64 + m] * LOG2E;
                         w1 = dwk[c1] * pwk[c1 * 64 + m] * LOG2E; }
    else               { const int m = nn - 128; w0 = dwv[c0] * pwv[c0 * 64 + m]; w1 = dwv[c1] * pwv[c1 * 64 + m]; }
    const int h = nn / 96, nl = nn % 96, nt = nl >> 3, r = nl & 7;
    const int ks = p >> 3, rem = p & 7, q = rem & 3, slot = rem >> 2;
    g_Wfrag[(((h * 12 + nt) * 16 + ks) * 32 + r * 4 + q) * 2 + slot] = packf16(w0, w1);
}

// ---------------------------------------------------------------------------
// 2) QKV projection via mma.sync (proven R6/R10)
// ---------------------------------------------------------------------------
__global__ __launch_bounds__(256) void proj_k(const float* __restrict__ X) {
    __shared__ uint32_t sW[12288];   // 48 KB
    const int tid = threadIdx.x, lane = tid & 31, w = tid >> 5;
    const int r = lane >> 2, q = lane & 3;
    const int m0 = blockIdx.x * 128, h = blockIdx.y;

    const uint32_t swb = s2u(sW);
    const uint32_t* Wsrc = g_Wfrag + h * 12288;
    for (int t = tid; t < 3072; t += 256) cpasync16(swb + t * 16, Wsrc + t * 4);
    cpcommit(); cpwait<0>(); __syncthreads();

    float acc[12][4];
#pragma unroll
    for (int nt = 0; nt < 12; nt++) {
        const int n0 = h * 96 + nt * 8 + 2 * q;
        const float b0 = g_b192[n0], b1 = g_b192[n0 + 1];
        acc[nt][0] = b0; acc[nt][1] = b1; acc[nt][2] = b0; acc[nt][3] = b1;
    }

    const int mA = m0 + 16 * w + r;
    const float2* X2 = (const float2*)X;
    const uint2* sW2 = (const uint2*)sW;
#pragma unroll 4
    for (int ks = 0; ks < 16; ks++) {
        const float2 u0 = X2[(size_t)mA * 128 + ks * 8 + q];
        const float2 u1 = X2[(size_t)(mA + 8) * 128 + ks * 8 + q];
        const float2 u2 = X2[(size_t)mA * 128 + ks * 8 + q + 4];
        const float2 u3 = X2[(size_t)(mA + 8) * 128 + ks * 8 + q + 4];
        const uint32_t a0 = packf16(u0.x, u0.y);
        const uint32_t a1 = packf16(u1.x, u1.y);
        const uint32_t a2 = packf16(u2.x, u2.y);
        const uint32_t a3 = packf16(u3.x, u3.y);
#pragma unroll
        for (int nt = 0; nt < 12; nt++) {
            const uint2 b = sW2[(nt * 16 + ks) * 32 + lane];
            mma16816(acc[nt][0], acc[nt][1], acc[nt][2], acc[nt][3], a0, a1, a2, a3, b.x, b.y);
        }
    }

    uint32_t* Qw = (uint32_t*)g_Qh;
    uint32_t* Kw = (uint32_t*)g_Kh;
    const int nb = mA >> 12, ii = mA & 4095;
#pragma unroll
    for (int nt = 0; nt < 12; nt++) {
        const int n0 = h * 96 + nt * 8 + 2 * q;
        if (n0 < 64) {
            Qw[(size_t)mA * 32 + (n0 >> 1)]       = packf16(acc[nt][0], acc[nt][1]);
            Qw[(size_t)(mA + 8) * 32 + (n0 >> 1)] = packf16(acc[nt][2], acc[nt][3]);
        } else if (n0 < 128) {
            const int k0 = n0 - 64;
            Kw[(size_t)mA * 32 + (k0 >> 1)]       = packf16(acc[nt][0], acc[nt][1]);
            Kw[(size_t)(mA + 8) * 32 + (k0 >> 1)] = packf16(acc[nt][2], acc[nt][3]);
        } else {
            const int c = n0 - 128;
            g_Vth[((size_t)nb * 64 + c) * HW + ii]          = __float2half(acc[nt][0]);
            g_Vth[((size_t)nb * 64 + c + 1) * HW + ii]      = __float2half(acc[nt][1]);
            g_Vth[((size_t)nb * 64 + c) * HW + ii + 8]      = __float2half(acc[nt][2]);
            g_Vth[((size_t)nb * 64 + c + 1) * HW + ii + 8]  = __float2half(acc[nt][3]);
        }
    }
}

// ---------------------------------------------------------------------------
// 3) Pass A: rowsum partials (R10/R13-proven). S' = S*log2e -> ex2.
// ---------------------------------------------------------------------------
__global__ __launch_bounds__(128, 4) void rowsum_k() {
    __shared__ uint32_t sQ[2][128 * 36];
    const int tid = threadIdx.x, lane = tid & 31, w = tid >> 5;
    const int r = lane >> 2, q = lane & 3;
    const int i0 = blockIdx.x * 128, jq = blockIdx.y, n = blockIdx.z;

    uint32_t a[2][4][4];
    const uint32_t* Kg = (const uint32_t*)g_Kh + (size_t)n * HW * 32;
#pragma unroll
    for (int s = 0; s < 2; s++)
#pragma unroll
        for (int ks = 0; ks < 4; ks++) {
            const uint32_t* kr = Kg + (size_t)(i0 + 32 * w + 16 * s + r) * 32 + ks * 8 + q;
            a[s][ks][0] = kr[0]; a[s][ks][1] = kr[256]; a[s][ks][2] = kr[4]; a[s][ks][3] = kr[260];
        }
    const uint32_t* Qg = (const uint32_t*)g_Qh + ((size_t)n * HW + jq * 1024) * 32;
    const uint32_t sqb0 = s2u(sQ[0]), sqb1 = s2u(sQ[1]);
    const uint32_t loff = (lane & 7) * 144 + (lane >> 3) * 16;

    auto issue = [&](int ch, uint32_t base) {
#pragma unroll
        for (int t = tid; t < 1024; t += 128) {
            const int row = t >> 3, c4 = (t & 7) * 4;
            cpasync16(base + row * 144 + c4 * 4, Qg + (size_t)(ch * 128 + row) * 32 + c4);
        }
    };
    issue(0, sqb0); cpcommit();

    float sA[2] = {0.f, 0.f}, sB[2] = {0.f, 0.f};
    for (int ch = 0; ch < 8; ch++) {
        if (ch < 7) { issue(ch + 1, (ch & 1) ? sqb0 : sqb1); cpcommit(); cpwait<1>(); }
        else cpwait<0>();
        __syncthreads();
        const uint32_t base = (ch & 1) ? sqb1 : sqb0;
#pragma unroll 4
        for (int nt = 0; nt < 16; nt++) {
            uint32_t b00, b10, b01, b11, b02, b12, b03, b13;
            ldsm_x4(b00, b10, b01, b11, base + nt * 1152 + loff);
            ldsm_x4(b02, b12, b03, b13, base + nt * 1152 + 64 + loff);
#pragma unroll
            for (int s = 0; s < 2; s++) {
                uint32_t d0 = 0u, d1 = 0u;
                mma16816h(d0, d1, a[s][0][0], a[s][0][1], a[s][0][2], a[s][0][3], b00, b10);
                mma16816h(d0, d1, a[s][1][0], a[s][1][1], a[s][1][2], a[s][1][3], b01, b11);
                mma16816h(d0, d1, a[s][2][0], a[s][2][1], a[s][2][2], a[s][2][3], b02, b12);
                mma16816h(d0, d1, a[s][3][0], a[s][3][1], a[s][3][2], a[s][3][3], b03, b13);
                const float2 f0 = unpackh2(d0), f1 = unpackh2(d1);
                sA[s] += fex2(f0.x) + fex2(f0.y);
                sB[s] += fex2(f1.x) + fex2(f1.y);
            }
        }
        __syncthreads();
    }
#pragma unroll
    for (int s = 0; s < 2; s++) {
        float va = sA[s], vb = sB[s];
        va += __shfl_xor_sync(0xffffffffu, va, 1);
        va += __shfl_xor_sync(0xffffffffu, va, 2);
        vb += __shfl_xor_sync(0xffffffffu, vb, 1);
        vb += __shfl_xor_sync(0xffffffffu, vb, 2);
        if (q == 0) {
            g_part[jq][n * HW + i0 + 32 * w + 16 * s + r]     = va;
            g_part[jq][n * HW + i0 + 32 * w + 16 * s + r + 8] = vb;
        }
    }
}

// ---------------------------------------------------------------------------
// 4) Pass B over an i-quarter (R13-proven core, 2-stage pipeline). P' scaled
//    in registers by an f16x2 inv-pair table (replaces scalev_k).
// ---------------------------------------------------------------------------
__global__ __launch_bounds__(128, 4) void attn_k() {
    __shared__ uint32_t sK[2][64 * 36];
    __shared__ uint32_t sVt[2][64 * 36];
    __shared__ uint32_t sInvP[512];   // f16x2 (64/rowsum) per i-pair of this quarter
    const int tid = threadIdx.x, lane = tid & 31, w = tid >> 5;
    const int r = lane >> 2, q = lane & 3;
    const int j0 = blockIdx.x * 128, ih = blockIdx.y, n = blockIdx.z;

    // inv-pair table (one-time; first in-loop __syncthreads orders it)
    for (int t = tid; t < 512; t += 128) {
        const int gi = n * HW + ih * 1024 + 2 * t;
        const float s0 = g_part[0][gi] + g_part[1][gi] + g_part[2][gi] + g_part[3][gi];
        const float s1 = g_part[0][gi + 1] + g_part[1][gi + 1] + g_part[2][gi + 1] + g_part[3][gi + 1];
        sInvP[t] = packf16(64.0f / s0, 64.0f / s1);
    }

    uint32_t aq[2][4][4];
    const uint32_t* Qg = (const uint32_t*)g_Qh + (size_t)n * HW * 32;
#pragma unroll
    for (int s = 0; s < 2; s++)
#pragma unroll
        for (int ks = 0; ks < 4; ks++) {
            const uint32_t* qr = Qg + (size_t)(j0 + 32 * w + 16 * s + r) * 32 + ks * 8 + q;
            aq[s][ks][0] = qr[0]; aq[s][ks][1] = qr[256]; aq[s][ks][2] = qr[4]; aq[s][ks][3] = qr[260];
        }
    const uint32_t* Kg = (const uint32_t*)g_Kh + (size_t)n * HW * 32;
    const uint32_t* Vg = (const uint32_t*)g_Vth + (size_t)n * CR * (HW / 2);

    const uint32_t skb[2] = {s2u(sK[0]),  s2u(sK[1])};
    const uint32_t svb[2] = {s2u(sVt[0]), s2u(sVt[1])};
    const uint32_t loff1 = (lane & 7) * 144 + (lane >> 3) * 16;
    const uint32_t loff2 = (lane & 7) * 144 + ((lane >> 3) & 1) * 16 + (lane >> 4) * 1152;

    auto issue = [&](int ch, int buf) {
        const int i0 = ih * 1024 + ch * 64;
#pragma unroll
        for (int t = tid; t < 512; t += 128) {
            const int row = t >> 3, c4 = (t & 7) * 4;
            cpasync16(skb[buf] + row * 144 + c4 * 4, Kg + (size_t)(i0 + row) * 32 + c4);
            cpasync16(svb[buf] + row * 144 + c4 * 4, Vg + (size_t)row * 2048 + (i0 >> 1) + c4);
        }
    };

    uint32_t acc[2][8][2];
#pragma unroll
    for (int s = 0; s < 2; s++)
#pragma unroll
        for (int ct = 0; ct < 8; ct++)
            acc[s][ct][0] = acc[s][ct][1] = 0u;

    issue(0, 0); cpcommit();
    for (int ch = 0; ch < 16; ch++) {
        if (ch < 15) { issue(ch + 1, (ch + 1) & 1); cpcommit(); cpwait<1>(); }
        else cpwait<0>();
        __syncthreads();
        const int buf = ch & 1;
        const uint32_t kb = skb[buf], vb = svb[buf];

#pragma unroll
        for (int ks2 = 0; ks2 < 4; ks2++) {
            uint32_t ap[2][4];
#pragma unroll
            for (int half = 0; half < 2; half++) {
                const int nt = 2 * ks2 + half;
                uint32_t b00, b10, b01, b11, b02, b12, b03, b13;
                ldsm_x4(b00, b10, b01, b11, kb + nt * 1152 + loff1);
                ldsm_x4(b02, b12, b03, b13, kb + nt * 1152 + 64 + loff1);
                const uint32_t ivp = sInvP[ch * 32 + nt * 4 + q];
#pragma unroll
                for (int s = 0; s < 2; s++) {
                    uint32_t d0 = 0u, d1 = 0u;
                    mma16816h(d0, d1, aq[s][0][0], aq[s][0][1], aq[s][0][2], aq[s][0][3], b00, b10);
                    mma16816h(d0, d1, aq[s][1][0], aq[s][1][1], aq[s][1][2], aq[s][1][3], b01, b11);
                    mma16816h(d0, d1, aq[s][2][0], aq[s][2][1], aq[s][2][2], aq[s][2][3], b02, b12);
                    mma16816h(d0, d1, aq[s][3][0], aq[s][3][1], aq[s][3][2], aq[s][3][3], b03, b13);
                    ap[s][half]     = hmul2u(ex2h2(d0), ivp);
                    ap[s][2 + half] = hmul2u(ex2h2(d1), ivp);
                }
            }
#pragma unroll
            for (int ctp = 0; ctp < 4; ctp++) {
                uint32_t v0, v1, v2, v3;
                ldsm_x4(v0, v1, v2, v3, vb + ctp * 2304 + ks2 * 32 + loff2);
#pragma unroll
                for (int s = 0; s < 2; s++) {
                    mma16816h(acc[s][2 * ctp][0], acc[s][2 * ctp][1],
                              ap[s][0], ap[s][2], ap[s][1], ap[s][3], v0, v1);
                    mma16816h(acc[s][2 * ctp + 1][0], acc[s][2 * ctp + 1][1],
                              ap[s][0], ap[s][2], ap[s][1], ap[s][3], v2, v3);
                }
            }
        }
        __syncthreads();
    }

    uint32_t* A2 = (uint32_t*)(g_attph[ih] + ((size_t)n * HW + j0) * CR);
#pragma unroll
    for (int s = 0; s < 2; s++) {
        const int jl = 32 * w + 16 * s + r;
#pragma unroll
        for (int ct = 0; ct < 8; ct++) {
            A2[(size_t)jl * 32 + ct * 4 + q]       = acc[s][ct][0];
            A2[(size_t)(jl + 8) * 32 + ct * 4 + q] = acc[s][ct][1];
        }
    }
}

// ---------------------------------------------------------------------------
// 5) Final (R13-proven): coalesced half2 partial reads; Wa f16 in registers.
// ---------------------------------------------------------------------------
__global__ __launch_bounds__(256) void final_k(const float* __restrict__ G,
                                               const float* __restrict__ ba,
                                               float* __restrict__ out) {
    __shared__ float sa[64][68];
    const int b = blockIdx.x;
    const int n = b >> 6, w = b & 63;
    const int tid = threadIdx.x;

    const uint32_t* P0 = (const uint32_t*)(g_attph[0] + ((size_t)n * HW + w * 64) * CR);
    const uint32_t* P1 = (const uint32_t*)(g_attph[1] + ((size_t)n * HW + w * 64) * CR);
    const uint32_t* P2 = (const uint32_t*)(g_attph[2] + ((size_t)n * HW + w * 64) * CR);
    const uint32_t* P3 = (const uint32_t*)(g_attph[3] + ((size_t)n * HW + w * 64) * CR);
    for (int idx = tid; idx < 2048; idx += 256) {
        const int cr = idx >> 5, h2 = idx & 31;
        const size_t o = (size_t)cr * 32 + h2;
        const float2 v0 = unpackh2(P0[o]);
        const float2 v1 = unpackh2(P1[o]);
        const float2 v2 = unpackh2(P2[o]);
        const float2 v3 = unpackh2(P3[o]);
        sa[2 * h2][cr]     = v0.x + v1.x + v2.x + v3.x;
        sa[2 * h2 + 1][cr] = v0.y + v1.y + v2.y + v3.y;
    }
    __syncthreads();

    float wa[64];
#pragma unroll
    for (int cr = 0; cr < 64; cr++) wa[cr] = __half2float(g_Wah[cr * CIN + tid]);
    const float vba = ba[tid];

    size_t gidx = ((size_t)n * HW + w) * CIN + tid;
    for (int h = 0; h < 64; h++) {
        float acc = vba;
        const float4* row = (const float4*)sa[h];
#pragma unroll
        for (int k = 0; k < 16; k++) {
            const float4 v = row[k];
            acc = fmaf(v.x, wa[4 * k],     acc);
            acc = fmaf(v.y, wa[4 * k + 1], acc);
            acc = fmaf(v.z, wa[4 * k + 2], acc);
            acc = fmaf(v.w, wa[4 * k + 3], acc);
        }
        const float g = G[gidx];
        out[gidx] = fmaf(g, acc, g);
        gidx += (size_t)64 * CIN;
    }
}

// ---------------------------------------------------------------------------
extern "C" void kernel_launch(void* const* d_in, const int* in_sizes, int n_in,
                              void* d_out, int out_size) {
    const float* X   = (const float*)d_in[0];
    const float* G   = (const float*)d_in[1];
    const float* dwq = (const float*)d_in[2];
    const float* pwq = (const float*)d_in[3];
    const float* bq  = (const float*)d_in[4];
    const float* dwk = (const float*)d_in[5];
    const float* pwk = (const float*)d_in[6];
    const float* bk  = (const float*)d_in[7];
    const float* dwv = (const float*)d_in[8];
    const float* pwv = (const float*)d_in[9];
    const float* bv  = (const float*)d_in[10];
    const float* dwa = (const float*)d_in[11];
    const float* pwa = (const float*)d_in[12];
    const float* ba  = (const float*)d_in[13];
    float* out = (float*)d_out;

    const int N = in_sizes[0] / (HW * CIN);   // 4

    fold_k<<<96, 256>>>(dwq, pwq, bq, dwk, pwk, bk, dwv, pwv, bv, dwa, pwa);
    proj_k<<<dim3((N * HW) / 128, 2), 256>>>(X);
    rowsum_k<<<dim3(HW / 128, 4, N), 128>>>();
    attn_k<<<dim3(HW / 128, 4, N), 128>>>();
    final_k<<<N * 64, 256>>>(G, ba, out);
}